// round 2
// baseline (speedup 1.0000x reference)
#include <cuda_runtime.h>
#include <math.h>

// Problem constants (fixed by reference: B=4, L=S=2048, D_MODEL=1024, H=16, E=64)
#define D_MODEL 1024
#define NHEADS  16
#define HDIM    64
#define BATCH   4
#define SEQLEN  2048
#define MROWS   (BATCH * SEQLEN)   // 8192

// Scratch (allocation-free rule: __device__ globals). 4 x 32 MB.
__device__ float g_Q [(size_t)MROWS * D_MODEL];
__device__ float g_K [(size_t)MROWS * D_MODEL];
__device__ float g_V [(size_t)MROWS * D_MODEL];
__device__ float g_AO[(size_t)MROWS * D_MODEL];

// ---------------------------------------------------------------------------
// GEMM + bias: C[M,N] = X[M,K] * W[K,N] + bias[N]
// M = 8192, N = K = 1024 (all divisible by tile dims; no bounds checks).
// Block tile 128x128, K-tile 16, 256 threads, 8x8 per-thread microtile with
// split layout (two 4-wide groups 64 apart) so LDS.128 reads are conflict-free.
// Double-buffered smem pipeline: GMEM->reg prefetch overlapped with compute,
// single __syncthreads per K-iteration.
// ---------------------------------------------------------------------------
__global__ __launch_bounds__(256) void gemm_bias_kernel(
    const float* __restrict__ X, const float* __restrict__ W,
    const float* __restrict__ bias, float* __restrict__ C)
{
    const int N = D_MODEL, K = D_MODEL;
    __shared__ float As[2][16][132];   // transposed A tile [k][m], padded
    __shared__ float Bs[2][16][128];   // B tile [k][n]

    const int tid = threadIdx.x;
    const int bm  = blockIdx.y * 128;
    const int bn  = blockIdx.x * 128;
    const int tx  = tid & 15;
    const int ty  = tid >> 4;

    // A-load mapping: thread handles rows arow0/arow1, 4 consecutive k each.
    const int arow0 = tid >> 1;              // 0..127 (for v = tid)
    const int akc0  = (tid & 1) << 2;        // 0 or 4
    const int arow1 = (256 + tid) >> 1 - 0;  // computed below properly
    // B-load mapping
    const int brow0 = tid >> 5;              // 0..7
    const int bcol0 = (tid & 31) << 2;       // 0..124

    float acc[8][8];
#pragma unroll
    for (int i = 0; i < 8; i++)
#pragma unroll
        for (int j = 0; j < 8; j++) acc[i][j] = 0.f;

    // ---- load K-tile 0 into buffer 0 ----
    {
#pragma unroll
        for (int i = 0; i < 2; i++) {
            int v   = i * 256 + tid;
            int row = v >> 2;                 // 0..127
            int kc  = (v & 3) << 2;           // 0,4,8,12
            float4 a = *(const float4*)(X + (size_t)(bm + row) * K + kc);
            As[0][kc + 0][row] = a.x;
            As[0][kc + 1][row] = a.y;
            As[0][kc + 2][row] = a.z;
            As[0][kc + 3][row] = a.w;
        }
#pragma unroll
        for (int i = 0; i < 2; i++) {
            int v   = i * 256 + tid;
            int row = v >> 5;                 // 0..15
            int col = (v & 31) << 2;          // 0..124
            *(float4*)(&Bs[0][row][col]) =
                *(const float4*)(W + (size_t)row * N + bn + col);
        }
    }
    __syncthreads();

    int cur = 0;
    const int NK = K / 16;   // 64
    for (int t = 0; t < NK; t++) {
        const int k0n = (t + 1) * 16;
        float4 pa[2], pb[2];
        if (t + 1 < NK) {
            // prefetch next tile GMEM -> registers
#pragma unroll
            for (int i = 0; i < 2; i++) {
                int v   = i * 256 + tid;
                int row = v >> 2;
                int kc  = (v & 3) << 2;
                pa[i] = *(const float4*)(X + (size_t)(bm + row) * K + k0n + kc);
            }
#pragma unroll
            for (int i = 0; i < 2; i++) {
                int v   = i * 256 + tid;
                int row = v >> 5;
                int col = (v & 31) << 2;
                pb[i] = *(const float4*)(W + (size_t)(k0n + row) * N + bn + col);
            }
        }

        // ---- compute on buffer cur ----
#pragma unroll
        for (int k = 0; k < 16; k++) {
            float4 a0 = *(float4*)(&As[cur][k][ty * 4]);
            float4 a1 = *(float4*)(&As[cur][k][64 + ty * 4]);
            float4 b0 = *(float4*)(&Bs[cur][k][tx * 4]);
            float4 b1 = *(float4*)(&Bs[cur][k][64 + tx * 4]);
            float ra[8] = {a0.x, a0.y, a0.z, a0.w, a1.x, a1.y, a1.z, a1.w};
            float rb[8] = {b0.x, b0.y, b0.z, b0.w, b1.x, b1.y, b1.z, b1.w};
#pragma unroll
            for (int i = 0; i < 8; i++)
#pragma unroll
                for (int j = 0; j < 8; j++)
                    acc[i][j] = fmaf(ra[i], rb[j], acc[i][j]);
        }

        if (t + 1 < NK) {
            const int nxt = cur ^ 1;
            // store prefetched regs -> other buffer
#pragma unroll
            for (int i = 0; i < 2; i++) {
                int v   = i * 256 + tid;
                int row = v >> 2;
                int kc  = (v & 3) << 2;
                As[nxt][kc + 0][row] = pa[i].x;
                As[nxt][kc + 1][row] = pa[i].y;
                As[nxt][kc + 2][row] = pa[i].z;
                As[nxt][kc + 3][row] = pa[i].w;
            }
#pragma unroll
            for (int i = 0; i < 2; i++) {
                int v   = i * 256 + tid;
                int row = v >> 5;
                int col = (v & 31) << 2;
                *(float4*)(&Bs[nxt][row][col]) = pb[i];
            }
            __syncthreads();
            cur = nxt;
        }
    }

    // Epilogue: bias + store (float4, coalesced).
#pragma unroll
    for (int jh = 0; jh < 2; jh++) {
        const int cb = bn + jh * 64 + tx * 4;
        float4 bv = *(const float4*)(bias + cb);
#pragma unroll
        for (int ih = 0; ih < 2; ih++) {
#pragma unroll
            for (int i = 0; i < 4; i++) {
                int r = bm + ih * 64 + ty * 4 + i;
                float4 o;
                o.x = acc[ih * 4 + i][jh * 4 + 0] + bv.x;
                o.y = acc[ih * 4 + i][jh * 4 + 1] + bv.y;
                o.z = acc[ih * 4 + i][jh * 4 + 2] + bv.z;
                o.w = acc[ih * 4 + i][jh * 4 + 3] + bv.w;
                *(float4*)(C + (size_t)r * N + cb) = o;
            }
        }
    }
}

// ---------------------------------------------------------------------------
// Flash attention (fp32, non-causal). One block = 64 query rows of one
// (batch, head). Streams S in 64-row tiles with online softmax.
// Q/K stored transposed in smem ([e][row], stride 68) so both GEMM-fragment
// reads are conflict-free float4s; P stored row-major, V row-major.
// ---------------------------------------------------------------------------
#define ATT_TILE   64
#define ATT_STRIDE 68
#define ATT_SMEM_BYTES (4 * ATT_TILE * ATT_STRIDE * 4)   // 69632 B

__global__ __launch_bounds__(256) void attention_kernel(
    const float* __restrict__ Q, const float* __restrict__ K,
    const float* __restrict__ V, float* __restrict__ O)
{
    extern __shared__ float smem[];
    float* Qt = smem;                                   // [64][68]  e-major
    float* Kt = smem + ATT_TILE * ATT_STRIDE;           // [64][68]  e-major
    float* Vs = smem + 2 * ATT_TILE * ATT_STRIDE;       // [64][68]  s-major
    float* Ps = smem + 3 * ATT_TILE * ATT_STRIDE;       // [64][68]  r-major

    const int tid = threadIdx.x;
    const int tx  = tid & 15;
    const int ty  = tid >> 4;
    const int b   = blockIdx.z;
    const int h   = blockIdx.y;
    const int q0  = blockIdx.x * ATT_TILE;

    // Load Q tile (64 x 64) transposed.
    const float* Qg = Q + ((size_t)b * SEQLEN + q0) * D_MODEL + h * HDIM;
#pragma unroll
    for (int i = 0; i < 4; i++) {
        int v = i * 256 + tid;
        int r = v >> 4;                 // 0..63
        int e = (v & 15) << 2;          // 0..60
        float4 q4 = *(const float4*)(Qg + (size_t)r * D_MODEL + e);
        Qt[(e + 0) * ATT_STRIDE + r] = q4.x;
        Qt[(e + 1) * ATT_STRIDE + r] = q4.y;
        Qt[(e + 2) * ATT_STRIDE + r] = q4.z;
        Qt[(e + 3) * ATT_STRIDE + r] = q4.w;
    }

    float m_i[4], l_i[4], acc[4][4];
#pragma unroll
    for (int i = 0; i < 4; i++) {
        m_i[i] = -1e30f;
        l_i[i] = 0.f;
#pragma unroll
        for (int j = 0; j < 4; j++) acc[i][j] = 0.f;
    }

    const float scale = 0.125f;   // 1/sqrt(64)

    for (int s0 = 0; s0 < SEQLEN; s0 += ATT_TILE) {
        const float* Kg = K + ((size_t)b * SEQLEN + s0) * D_MODEL + h * HDIM;
        const float* Vg = V + ((size_t)b * SEQLEN + s0) * D_MODEL + h * HDIM;

        __syncthreads();   // previous PV reads of Vs/Ps done before overwrite
#pragma unroll
        for (int i = 0; i < 4; i++) {
            int v = i * 256 + tid;
            int r = v >> 4;
            int e = (v & 15) << 2;
            float4 k4 = *(const float4*)(Kg + (size_t)r * D_MODEL + e);
            Kt[(e + 0) * ATT_STRIDE + r] = k4.x;
            Kt[(e + 1) * ATT_STRIDE + r] = k4.y;
            Kt[(e + 2) * ATT_STRIDE + r] = k4.z;
            Kt[(e + 3) * ATT_STRIDE + r] = k4.w;
            float4 v4 = *(const float4*)(Vg + (size_t)r * D_MODEL + e);
            *(float4*)(Vs + r * ATT_STRIDE + e) = v4;
        }
        __syncthreads();

        // S = Q K^T  (64x64x64), 4x4 per thread
        float sc[4][4];
#pragma unroll
        for (int i = 0; i < 4; i++)
#pragma unroll
            for (int j = 0; j < 4; j++) sc[i][j] = 0.f;

#pragma unroll 16
        for (int e = 0; e < ATT_TILE; e++) {
            float4 qa = *(float4*)(Qt + e * ATT_STRIDE + ty * 4);
            float4 kb = *(float4*)(Kt + e * ATT_STRIDE + tx * 4);
            float ra[4] = {qa.x, qa.y, qa.z, qa.w};
            float rb[4] = {kb.x, kb.y, kb.z, kb.w};
#pragma unroll
            for (int i = 0; i < 4; i++)
#pragma unroll
                for (int j = 0; j < 4; j++)
                    sc[i][j] = fmaf(ra[i], rb[j], sc[i][j]);
        }

        // Online softmax update (rows split across the 16-lane tx groups)
#pragma unroll
        for (int i = 0; i < 4; i++) {
            float s0v = sc[i][0] * scale;
            float s1v = sc[i][1] * scale;
            float s2v = sc[i][2] * scale;
            float s3v = sc[i][3] * scale;
            float rm = fmaxf(fmaxf(s0v, s1v), fmaxf(s2v, s3v));
#pragma unroll
            for (int o = 1; o < 16; o <<= 1)
                rm = fmaxf(rm, __shfl_xor_sync(0xffffffffu, rm, o));
            float mn = fmaxf(m_i[i], rm);
            float corr = __expf(m_i[i] - mn);
            m_i[i] = mn;
            float p0 = __expf(s0v - mn);
            float p1 = __expf(s1v - mn);
            float p2 = __expf(s2v - mn);
            float p3 = __expf(s3v - mn);
            float rs = (p0 + p1) + (p2 + p3);
#pragma unroll
            for (int o = 1; o < 16; o <<= 1)
                rs += __shfl_xor_sync(0xffffffffu, rs, o);
            l_i[i] = l_i[i] * corr + rs;
            acc[i][0] *= corr;
            acc[i][1] *= corr;
            acc[i][2] *= corr;
            acc[i][3] *= corr;
            *(float4*)(Ps + (ty * 4 + i) * ATT_STRIDE + tx * 4) =
                make_float4(p0, p1, p2, p3);
        }
        __syncthreads();

        // O += P V  (64x64x64)
#pragma unroll 16
        for (int s = 0; s < ATT_TILE; s++) {
            float4 vb = *(float4*)(Vs + s * ATT_STRIDE + tx * 4);
#pragma unroll
            for (int i = 0; i < 4; i++) {
                float p = Ps[(ty * 4 + i) * ATT_STRIDE + s];   // broadcast read
                acc[i][0] = fmaf(p, vb.x, acc[i][0]);
                acc[i][1] = fmaf(p, vb.y, acc[i][1]);
                acc[i][2] = fmaf(p, vb.z, acc[i][2]);
                acc[i][3] = fmaf(p, vb.w, acc[i][3]);
            }
        }
    }

    // Normalize and write out (concatenated-head layout [B*L, H*E]).
    float* Og = O + ((size_t)b * SEQLEN + q0) * D_MODEL + h * HDIM;
#pragma unroll
    for (int i = 0; i < 4; i++) {
        float inv = 1.0f / l_i[i];
        float4 o = make_float4(acc[i][0] * inv, acc[i][1] * inv,
                               acc[i][2] * inv, acc[i][3] * inv);
        *(float4*)(Og + (size_t)(ty * 4 + i) * D_MODEL + tx * 4) = o;
    }
}

// ---------------------------------------------------------------------------
// Launch: Q/K/V projections -> flash attention -> output projection.
// All launches on the default stream (graph-capturable: kernels only).
// ---------------------------------------------------------------------------
extern "C" void kernel_launch(void* const* d_in, const int* in_sizes, int n_in,
                              void* d_out, int out_size)
{
    (void)in_sizes; (void)n_in; (void)out_size;
    const float* queries = (const float*)d_in[0];
    const float* keys    = (const float*)d_in[1];
    const float* values  = (const float*)d_in[2];
    const float* Wq = (const float*)d_in[3];
    const float* bq = (const float*)d_in[4];
    const float* Wk = (const float*)d_in[5];
    const float* bk = (const float*)d_in[6];
    const float* Wv = (const float*)d_in[7];
    const float* bv = (const float*)d_in[8];
    const float* Wo = (const float*)d_in[9];
    const float* bo = (const float*)d_in[10];
    float* out = (float*)d_out;

    float *Qp, *Kp, *Vp, *AOp;
    cudaGetSymbolAddress((void**)&Qp,  g_Q);
    cudaGetSymbolAddress((void**)&Kp,  g_K);
    cudaGetSymbolAddress((void**)&Vp,  g_V);
    cudaGetSymbolAddress((void**)&AOp, g_AO);

    cudaFuncSetAttribute(attention_kernel,
                         cudaFuncAttributeMaxDynamicSharedMemorySize,
                         ATT_SMEM_BYTES);

    dim3 gg(D_MODEL / 128, MROWS / 128);   // (8, 64)
    gemm_bias_kernel<<<gg, 256>>>(queries, Wq, bq, Qp);
    gemm_bias_kernel<<<gg, 256>>>(keys,    Wk, bk, Kp);
    gemm_bias_kernel<<<gg, 256>>>(values,  Wv, bv, Vp);

    dim3 ga(SEQLEN / ATT_TILE, NHEADS, BATCH);  // (32, 16, 4)
    attention_kernel<<<ga, 256, ATT_SMEM_BYTES>>>(Qp, Kp, Vp, AOp);

    gemm_bias_kernel<<<gg, 256>>>(AOp, Wo, bo, out);
}

// round 4
// speedup vs baseline: 1.2526x; 1.2526x over previous
#include <cuda_runtime.h>
#include <cstdint>
#include <math.h>

// Problem constants (fixed by reference: B=4, L=S=2048, D_MODEL=1024, H=16, E=64)
#define D_MODEL 1024
#define NHEADS  16
#define HDIM    64
#define BATCH   4
#define SEQLEN  2048
#define MROWS   (BATCH * SEQLEN)   // 8192

// Scratch (allocation-free rule: __device__ globals). 4 x 32 MB.
__device__ float g_Q [(size_t)MROWS * D_MODEL];
__device__ float g_K [(size_t)MROWS * D_MODEL];
__device__ float g_V [(size_t)MROWS * D_MODEL];
__device__ float g_AO[(size_t)MROWS * D_MODEL];

__device__ __forceinline__ uint32_t cvt_tf32(float f) {
    uint32_t r;
    asm("cvt.rna.tf32.f32 %0, %1;" : "=r"(r) : "f"(f));
    return r;
}

// ===========================================================================
// tf32 mma.sync GEMM + bias: C[M,N] = X[M,K] * W[K,N] + bias[N]
// M=8192, N=K=1024. CTA 128x128, K-chunk 32, 8 warps (2m x 4n), warp tile
// 64x32 = 4x4 tiles of mma.sync.m16n8k8.tf32. SMEM stride 36 floats makes
// all fragment LDS and staging STS bank-conflict-free. Double-buffered.
// ===========================================================================
#define GS   36                      // smem row stride in floats
#define KC   32                      // K per chunk
#define NCHK (D_MODEL / KC)          // 32 chunks
#define ABUF (128 * GS)              // 4608 floats per A (or B) buffer
#define GEMM_SMEM (4 * ABUF * 4)     // 73728 bytes

__global__ __launch_bounds__(256) void gemm_tf32_kernel(
    const float* __restrict__ X, const float* __restrict__ W,
    const float* __restrict__ bias, float* __restrict__ C)
{
    extern __shared__ float sm[];
    float* Abuf[2] = { sm,            sm + 2 * ABUF };
    float* Bbuf[2] = { sm + ABUF,     sm + 3 * ABUF };

    const int tid = threadIdx.x;
    const int w   = tid >> 5;        // warp 0..7
    const int l   = tid & 31;
    const int g   = l >> 2;          // groupID 0..7
    const int d   = l & 3;           // threadID_in_group 0..3
    const int wm  = w & 1;           // warp m-row (0..1) -> 64 rows each
    const int wn  = w >> 1;          // warp n-col (0..3) -> 32 cols each
    const int bm  = blockIdx.y * 128;
    const int bn  = blockIdx.x * 128;

    // B staging geometry (per warp: n in [16w,16w+16), k quads via g>>2 and d)
    const int bn_off = 16 * w + 4 * (g & 3);     // n base of this lane's float4
    const int bk_off = d + 4 * (g >> 2);         // k row within 8-row group

    float c[4][4][4];
#pragma unroll
    for (int mt = 0; mt < 4; mt++)
#pragma unroll
        for (int nt = 0; nt < 4; nt++)
#pragma unroll
            for (int r = 0; r < 4; r++) c[mt][nt][r] = 0.f;

    uint4  ar[4];   // A chunk, tf32-converted
    float4 br[4];   // B chunk, raw (transpose+convert at STS)

    // ---- staging helpers (macros keep everything in registers) ----
#define LDG_A(kc) do {                                                        \
    _Pragma("unroll")                                                         \
    for (int i = 0; i < 4; i++) {                                             \
        int v = i * 256 + tid; int row = v >> 3; int kq = (v & 7) << 2;       \
        float4 a = *(const float4*)(X + (size_t)(bm + row) * D_MODEL + (kc) + kq); \
        ar[i] = make_uint4(cvt_tf32(a.x), cvt_tf32(a.y),                      \
                           cvt_tf32(a.z), cvt_tf32(a.w));                     \
    } } while (0)

#define LDG_B(kc) do {                                                        \
    _Pragma("unroll")                                                         \
    for (int i = 0; i < 4; i++) {                                             \
        int k = bk_off + 8 * i;                                               \
        br[i] = *(const float4*)(W + (size_t)((kc) + k) * D_MODEL + bn + bn_off); \
    } } while (0)

#define STS_A(dst) do {                                                       \
    _Pragma("unroll")                                                         \
    for (int i = 0; i < 4; i++) {                                             \
        int v = i * 256 + tid; int row = v >> 3; int kq = (v & 7) << 2;       \
        *(uint4*)((dst) + row * GS + kq) = ar[i];                             \
    } } while (0)

    // 4x4 butterfly transpose within each quad, then tf32-convert and store.
#define STS_B(dst) do {                                                       \
    _Pragma("unroll")                                                         \
    for (int i = 0; i < 4; i++) {                                             \
        float e0 = br[i].x, e1 = br[i].y, e2 = br[i].z, e3 = br[i].w;         \
        float s, rcv;                                                         \
        s = (d & 1) ? e0 : e1; rcv = __shfl_xor_sync(0xffffffffu, s, 1);      \
        if (d & 1) e0 = rcv; else e1 = rcv;                                   \
        s = (d & 1) ? e2 : e3; rcv = __shfl_xor_sync(0xffffffffu, s, 1);      \
        if (d & 1) e2 = rcv; else e3 = rcv;                                   \
        s = (d & 2) ? e0 : e2; rcv = __shfl_xor_sync(0xffffffffu, s, 2);      \
        if (d & 2) e0 = rcv; else e2 = rcv;                                   \
        s = (d & 2) ? e1 : e3; rcv = __shfl_xor_sync(0xffffffffu, s, 2);      \
        if (d & 2) e1 = rcv; else e3 = rcv;                                   \
        int kb = 4 * (g >> 2) + 8 * i;                                        \
        int n  = 16 * w + 4 * (g & 3) + d;                                    \
        *(uint4*)((dst) + n * GS + kb) =                                      \
            make_uint4(cvt_tf32(e0), cvt_tf32(e1), cvt_tf32(e2), cvt_tf32(e3)); \
    } } while (0)

    // ---- prologue: stage chunk 0 ----
    LDG_A(0); LDG_B(0);
    STS_A(Abuf[0]); STS_B(Bbuf[0]);
    __syncthreads();

#pragma unroll 1
    for (int t = 0; t < NCHK; t++) {
        const int cur = t & 1;
        const float* Ab = Abuf[cur];
        const float* Bb = Bbuf[cur];

        if (t + 1 < NCHK) { LDG_A((t + 1) * KC); LDG_B((t + 1) * KC); }

        // ---- compute chunk (4 k-steps of k8) ----
#pragma unroll
        for (int kk = 0; kk < 4; kk++) {
            const int ko = kk * 8;
            uint32_t af[4][4];
#pragma unroll
            for (int mt = 0; mt < 4; mt++) {
                const float* p = Ab + (wm * 64 + mt * 16 + g) * GS + ko + d;
                af[mt][0] = __float_as_uint(p[0]);
                af[mt][1] = __float_as_uint(p[8 * GS]);
                af[mt][2] = __float_as_uint(p[4]);
                af[mt][3] = __float_as_uint(p[8 * GS + 4]);
            }
            uint32_t bf[4][2];
#pragma unroll
            for (int nt = 0; nt < 4; nt++) {
                const float* p = Bb + (wn * 32 + nt * 8 + g) * GS + ko + d;
                bf[nt][0] = __float_as_uint(p[0]);
                bf[nt][1] = __float_as_uint(p[4]);
            }
#pragma unroll
            for (int mt = 0; mt < 4; mt++)
#pragma unroll
                for (int nt = 0; nt < 4; nt++) {
                    asm volatile(
                        "mma.sync.aligned.m16n8k8.row.col.f32.tf32.tf32.f32 "
                        "{%0,%1,%2,%3}, {%4,%5,%6,%7}, {%8,%9}, {%0,%1,%2,%3};\n"
                        : "+f"(c[mt][nt][0]), "+f"(c[mt][nt][1]),
                          "+f"(c[mt][nt][2]), "+f"(c[mt][nt][3])
                        : "r"(af[mt][0]), "r"(af[mt][1]),
                          "r"(af[mt][2]), "r"(af[mt][3]),
                          "r"(bf[nt][0]), "r"(bf[nt][1]));
                }
        }

        if (t + 1 < NCHK) {
            STS_A(Abuf[cur ^ 1]); STS_B(Bbuf[cur ^ 1]);
            __syncthreads();
        }
    }

    // ---- epilogue: bias + store ----
#pragma unroll
    for (int nt = 0; nt < 4; nt++) {
        const int col = bn + wn * 32 + nt * 8 + 2 * d;
        const float2 bb = *(const float2*)(bias + col);
#pragma unroll
        for (int mt = 0; mt < 4; mt++) {
            const int r0 = bm + wm * 64 + mt * 16 + g;
            float2 o0, o1;
            o0.x = c[mt][nt][0] + bb.x; o0.y = c[mt][nt][1] + bb.y;
            o1.x = c[mt][nt][2] + bb.x; o1.y = c[mt][nt][3] + bb.y;
            *(float2*)(C + (size_t)r0 * D_MODEL + col)       = o0;
            *(float2*)(C + (size_t)(r0 + 8) * D_MODEL + col) = o1;
        }
    }
#undef LDG_A
#undef LDG_B
#undef STS_A
#undef STS_B
}

// ---------------------------------------------------------------------------
// Flash attention (fp32, non-causal) — unchanged from the passing R2 kernel.
// ---------------------------------------------------------------------------
#define ATT_TILE   64
#define ATT_STRIDE 68
#define ATT_SMEM_BYTES (4 * ATT_TILE * ATT_STRIDE * 4)   // 69632 B

__global__ __launch_bounds__(256) void attention_kernel(
    const float* __restrict__ Q, const float* __restrict__ K,
    const float* __restrict__ V, float* __restrict__ O)
{
    extern __shared__ float smemf[];
    float* Qt = smemf;
    float* Kt = smemf + ATT_TILE * ATT_STRIDE;
    float* Vs = smemf + 2 * ATT_TILE * ATT_STRIDE;
    float* Ps = smemf + 3 * ATT_TILE * ATT_STRIDE;

    const int tid = threadIdx.x;
    const int tx  = tid & 15;
    const int ty  = tid >> 4;
    const int b   = blockIdx.z;
    const int h   = blockIdx.y;
    const int q0  = blockIdx.x * ATT_TILE;

    const float* Qg = Q + ((size_t)b * SEQLEN + q0) * D_MODEL + h * HDIM;
#pragma unroll
    for (int i = 0; i < 4; i++) {
        int v = i * 256 + tid;
        int r = v >> 4;
        int e = (v & 15) << 2;
        float4 q4 = *(const float4*)(Qg + (size_t)r * D_MODEL + e);
        Qt[(e + 0) * ATT_STRIDE + r] = q4.x;
        Qt[(e + 1) * ATT_STRIDE + r] = q4.y;
        Qt[(e + 2) * ATT_STRIDE + r] = q4.z;
        Qt[(e + 3) * ATT_STRIDE + r] = q4.w;
    }

    float m_i[4], l_i[4], acc[4][4];
#pragma unroll
    for (int i = 0; i < 4; i++) {
        m_i[i] = -1e30f;
        l_i[i] = 0.f;
#pragma unroll
        for (int j = 0; j < 4; j++) acc[i][j] = 0.f;
    }

    const float scale = 0.125f;

    for (int s0 = 0; s0 < SEQLEN; s0 += ATT_TILE) {
        const float* Kg = K + ((size_t)b * SEQLEN + s0) * D_MODEL + h * HDIM;
        const float* Vg = V + ((size_t)b * SEQLEN + s0) * D_MODEL + h * HDIM;

        __syncthreads();
#pragma unroll
        for (int i = 0; i < 4; i++) {
            int v = i * 256 + tid;
            int r = v >> 4;
            int e = (v & 15) << 2;
            float4 k4 = *(const float4*)(Kg + (size_t)r * D_MODEL + e);
            Kt[(e + 0) * ATT_STRIDE + r] = k4.x;
            Kt[(e + 1) * ATT_STRIDE + r] = k4.y;
            Kt[(e + 2) * ATT_STRIDE + r] = k4.z;
            Kt[(e + 3) * ATT_STRIDE + r] = k4.w;
            float4 v4 = *(const float4*)(Vg + (size_t)r * D_MODEL + e);
            *(float4*)(Vs + r * ATT_STRIDE + e) = v4;
        }
        __syncthreads();

        float sc[4][4];
#pragma unroll
        for (int i = 0; i < 4; i++)
#pragma unroll
            for (int j = 0; j < 4; j++) sc[i][j] = 0.f;

#pragma unroll 16
        for (int e = 0; e < ATT_TILE; e++) {
            float4 qa = *(float4*)(Qt + e * ATT_STRIDE + ty * 4);
            float4 kb = *(float4*)(Kt + e * ATT_STRIDE + tx * 4);
            float ra[4] = {qa.x, qa.y, qa.z, qa.w};
            float rb[4] = {kb.x, kb.y, kb.z, kb.w};
#pragma unroll
            for (int i = 0; i < 4; i++)
#pragma unroll
                for (int j = 0; j < 4; j++)
                    sc[i][j] = fmaf(ra[i], rb[j], sc[i][j]);
        }

#pragma unroll
        for (int i = 0; i < 4; i++) {
            float s0v = sc[i][0] * scale;
            float s1v = sc[i][1] * scale;
            float s2v = sc[i][2] * scale;
            float s3v = sc[i][3] * scale;
            float rm = fmaxf(fmaxf(s0v, s1v), fmaxf(s2v, s3v));
#pragma unroll
            for (int o = 1; o < 16; o <<= 1)
                rm = fmaxf(rm, __shfl_xor_sync(0xffffffffu, rm, o));
            float mn = fmaxf(m_i[i], rm);
            float corr = __expf(m_i[i] - mn);
            m_i[i] = mn;
            float p0 = __expf(s0v - mn);
            float p1 = __expf(s1v - mn);
            float p2 = __expf(s2v - mn);
            float p3 = __expf(s3v - mn);
            float rs = (p0 + p1) + (p2 + p3);
#pragma unroll
            for (int o = 1; o < 16; o <<= 1)
                rs += __shfl_xor_sync(0xffffffffu, rs, o);
            l_i[i] = l_i[i] * corr + rs;
            acc[i][0] *= corr;
            acc[i][1] *= corr;
            acc[i][2] *= corr;
            acc[i][3] *= corr;
            *(float4*)(Ps + (ty * 4 + i) * ATT_STRIDE + tx * 4) =
                make_float4(p0, p1, p2, p3);
        }
        __syncthreads();

#pragma unroll 16
        for (int s = 0; s < ATT_TILE; s++) {
            float4 vb = *(float4*)(Vs + s * ATT_STRIDE + tx * 4);
#pragma unroll
            for (int i = 0; i < 4; i++) {
                float p = Ps[(ty * 4 + i) * ATT_STRIDE + s];
                acc[i][0] = fmaf(p, vb.x, acc[i][0]);
                acc[i][1] = fmaf(p, vb.y, acc[i][1]);
                acc[i][2] = fmaf(p, vb.z, acc[i][2]);
                acc[i][3] = fmaf(p, vb.w, acc[i][3]);
            }
        }
    }

    float* Og = O + ((size_t)b * SEQLEN + q0) * D_MODEL + h * HDIM;
#pragma unroll
    for (int i = 0; i < 4; i++) {
        float inv = 1.0f / l_i[i];
        float4 o = make_float4(acc[i][0] * inv, acc[i][1] * inv,
                               acc[i][2] * inv, acc[i][3] * inv);
        *(float4*)(Og + (size_t)(ty * 4 + i) * D_MODEL + tx * 4) = o;
    }
}

// ---------------------------------------------------------------------------
// Launch: tf32 mma.sync projections -> fp32 flash attention -> out proj.
// ---------------------------------------------------------------------------
extern "C" void kernel_launch(void* const* d_in, const int* in_sizes, int n_in,
                              void* d_out, int out_size)
{
    (void)in_sizes; (void)n_in; (void)out_size;
    const float* queries = (const float*)d_in[0];
    const float* keys    = (const float*)d_in[1];
    const float* values  = (const float*)d_in[2];
    const float* Wq = (const float*)d_in[3];
    const float* bq = (const float*)d_in[4];
    const float* Wk = (const float*)d_in[5];
    const float* bk = (const float*)d_in[6];
    const float* Wv = (const float*)d_in[7];
    const float* bv = (const float*)d_in[8];
    const float* Wo = (const float*)d_in[9];
    const float* bo = (const float*)d_in[10];
    float* out = (float*)d_out;

    float *Qp, *Kp, *Vp, *AOp;
    cudaGetSymbolAddress((void**)&Qp,  g_Q);
    cudaGetSymbolAddress((void**)&Kp,  g_K);
    cudaGetSymbolAddress((void**)&Vp,  g_V);
    cudaGetSymbolAddress((void**)&AOp, g_AO);

    cudaFuncSetAttribute(gemm_tf32_kernel,
                         cudaFuncAttributeMaxDynamicSharedMemorySize, GEMM_SMEM);
    cudaFuncSetAttribute(attention_kernel,
                         cudaFuncAttributeMaxDynamicSharedMemorySize, ATT_SMEM_BYTES);

    dim3 gg(D_MODEL / 128, MROWS / 128);   // (8, 64)
    gemm_tf32_kernel<<<gg, 256, GEMM_SMEM>>>(queries, Wq, bq, Qp);
    gemm_tf32_kernel<<<gg, 256, GEMM_SMEM>>>(keys,    Wk, bk, Kp);
    gemm_tf32_kernel<<<gg, 256, GEMM_SMEM>>>(values,  Wv, bv, Vp);

    dim3 ga(SEQLEN / ATT_TILE, NHEADS, BATCH);  // (32, 16, 4)
    attention_kernel<<<ga, 256, ATT_SMEM_BYTES>>>(Qp, Kp, Vp, AOp);

    gemm_tf32_kernel<<<gg, 256, GEMM_SMEM>>>(AOp, Wo, bo, out);
}

// round 6
// speedup vs baseline: 2.6512x; 2.1166x over previous
#include <cuda_runtime.h>
#include <cstdint>
#include <math.h>

// Problem constants (fixed by reference: B=4, L=S=2048, D_MODEL=1024, H=16, E=64)
#define D_MODEL 1024
#define NHEADS  16
#define HDIM    64
#define BATCH   4
#define SEQLEN  2048
#define MROWS   (BATCH * SEQLEN)   // 8192

// Scratch (allocation-free rule: __device__ globals). 4 x 32 MB.
__device__ float g_Q [(size_t)MROWS * D_MODEL];
__device__ float g_K [(size_t)MROWS * D_MODEL];
__device__ float g_V [(size_t)MROWS * D_MODEL];
__device__ float g_AO[(size_t)MROWS * D_MODEL];

__device__ __forceinline__ uint32_t cvt_tf32(float f) {
    uint32_t r;
    asm("cvt.rna.tf32.f32 %0, %1;" : "=r"(r) : "f"(f));
    return r;
}

#define MMA_TF32(cc, a0, a1, a2, a3, b0, b1)                                  \
    asm volatile(                                                             \
        "mma.sync.aligned.m16n8k8.row.col.f32.tf32.tf32.f32 "                 \
        "{%0,%1,%2,%3}, {%4,%5,%6,%7}, {%8,%9}, {%0,%1,%2,%3};\n"             \
        : "+f"((cc)[0]), "+f"((cc)[1]), "+f"((cc)[2]), "+f"((cc)[3])          \
        : "r"(a0), "r"(a1), "r"(a2), "r"(a3), "r"(b0), "r"(b1))

// ===========================================================================
// tf32 mma.sync GEMM + bias (unchanged from passing R4 kernel).
// C[M,N] = X[M,K] * W[K,N] + bias[N]; M=8192, N=K=1024. CTA 128x128,
// K-chunk 32, 8 warps (2m x 4n), warp tile 64x32 of m16n8k8.tf32.
// ===========================================================================
#define GS   36
#define KC   32
#define NCHK (D_MODEL / KC)
#define ABUF (128 * GS)
#define GEMM_SMEM (4 * ABUF * 4)     // 73728 bytes

__global__ __launch_bounds__(256) void gemm_tf32_kernel(
    const float* __restrict__ X, const float* __restrict__ W,
    const float* __restrict__ bias, float* __restrict__ C)
{
    extern __shared__ float sm[];
    float* Abuf[2] = { sm,            sm + 2 * ABUF };
    float* Bbuf[2] = { sm + ABUF,     sm + 3 * ABUF };

    const int tid = threadIdx.x;
    const int w   = tid >> 5;
    const int l   = tid & 31;
    const int g   = l >> 2;
    const int d   = l & 3;
    const int wm  = w & 1;
    const int wn  = w >> 1;
    const int bm  = blockIdx.y * 128;
    const int bn  = blockIdx.x * 128;

    const int bn_off = 16 * w + 4 * (g & 3);
    const int bk_off = d + 4 * (g >> 2);

    float c[4][4][4];
#pragma unroll
    for (int mt = 0; mt < 4; mt++)
#pragma unroll
        for (int nt = 0; nt < 4; nt++)
#pragma unroll
            for (int r = 0; r < 4; r++) c[mt][nt][r] = 0.f;

    uint4  ar[4];
    float4 br[4];

#define LDG_A(kc) do {                                                        \
    _Pragma("unroll")                                                         \
    for (int i = 0; i < 4; i++) {                                             \
        int v = i * 256 + tid; int row = v >> 3; int kq = (v & 7) << 2;       \
        float4 a = *(const float4*)(X + (size_t)(bm + row) * D_MODEL + (kc) + kq); \
        ar[i] = make_uint4(cvt_tf32(a.x), cvt_tf32(a.y),                      \
                           cvt_tf32(a.z), cvt_tf32(a.w));                     \
    } } while (0)

#define LDG_B(kc) do {                                                        \
    _Pragma("unroll")                                                         \
    for (int i = 0; i < 4; i++) {                                             \
        int k = bk_off + 8 * i;                                               \
        br[i] = *(const float4*)(W + (size_t)((kc) + k) * D_MODEL + bn + bn_off); \
    } } while (0)

#define STS_A(dst) do {                                                       \
    _Pragma("unroll")                                                         \
    for (int i = 0; i < 4; i++) {                                             \
        int v = i * 256 + tid; int row = v >> 3; int kq = (v & 7) << 2;       \
        *(uint4*)((dst) + row * GS + kq) = ar[i];                             \
    } } while (0)

#define STS_B(dst) do {                                                       \
    _Pragma("unroll")                                                         \
    for (int i = 0; i < 4; i++) {                                             \
        float e0 = br[i].x, e1 = br[i].y, e2 = br[i].z, e3 = br[i].w;         \
        float s, rcv;                                                         \
        s = (d & 1) ? e0 : e1; rcv = __shfl_xor_sync(0xffffffffu, s, 1);      \
        if (d & 1) e0 = rcv; else e1 = rcv;                                   \
        s = (d & 1) ? e2 : e3; rcv = __shfl_xor_sync(0xffffffffu, s, 1);      \
        if (d & 1) e2 = rcv; else e3 = rcv;                                   \
        s = (d & 2) ? e0 : e2; rcv = __shfl_xor_sync(0xffffffffu, s, 2);      \
        if (d & 2) e0 = rcv; else e2 = rcv;                                   \
        s = (d & 2) ? e1 : e3; rcv = __shfl_xor_sync(0xffffffffu, s, 2);      \
        if (d & 2) e1 = rcv; else e3 = rcv;                                   \
        int kb = 4 * (g >> 2) + 8 * i;                                        \
        int n  = 16 * w + 4 * (g & 3) + d;                                    \
        *(uint4*)((dst) + n * GS + kb) =                                      \
            make_uint4(cvt_tf32(e0), cvt_tf32(e1), cvt_tf32(e2), cvt_tf32(e3)); \
    } } while (0)

    LDG_A(0); LDG_B(0);
    STS_A(Abuf[0]); STS_B(Bbuf[0]);
    __syncthreads();

#pragma unroll 1
    for (int t = 0; t < NCHK; t++) {
        const int cur = t & 1;
        const float* Ab = Abuf[cur];
        const float* Bb = Bbuf[cur];

        if (t + 1 < NCHK) { LDG_A((t + 1) * KC); LDG_B((t + 1) * KC); }

#pragma unroll
        for (int kk = 0; kk < 4; kk++) {
            const int ko = kk * 8;
            uint32_t af[4][4];
#pragma unroll
            for (int mt = 0; mt < 4; mt++) {
                const float* p = Ab + (wm * 64 + mt * 16 + g) * GS + ko + d;
                af[mt][0] = __float_as_uint(p[0]);
                af[mt][1] = __float_as_uint(p[8 * GS]);
                af[mt][2] = __float_as_uint(p[4]);
                af[mt][3] = __float_as_uint(p[8 * GS + 4]);
            }
            uint32_t bf[4][2];
#pragma unroll
            for (int nt = 0; nt < 4; nt++) {
                const float* p = Bb + (wn * 32 + nt * 8 + g) * GS + ko + d;
                bf[nt][0] = __float_as_uint(p[0]);
                bf[nt][1] = __float_as_uint(p[4]);
            }
#pragma unroll
            for (int mt = 0; mt < 4; mt++)
#pragma unroll
                for (int nt = 0; nt < 4; nt++)
                    MMA_TF32(c[mt][nt], af[mt][0], af[mt][1], af[mt][2],
                             af[mt][3], bf[nt][0], bf[nt][1]);
        }

        if (t + 1 < NCHK) {
            STS_A(Abuf[cur ^ 1]); STS_B(Bbuf[cur ^ 1]);
            __syncthreads();
        }
    }

#pragma unroll
    for (int nt = 0; nt < 4; nt++) {
        const int col = bn + wn * 32 + nt * 8 + 2 * d;
        const float2 bb = *(const float2*)(bias + col);
#pragma unroll
        for (int mt = 0; mt < 4; mt++) {
            const int r0 = bm + wm * 64 + mt * 16 + g;
            float2 o0, o1;
            o0.x = c[mt][nt][0] + bb.x; o0.y = c[mt][nt][1] + bb.y;
            o1.x = c[mt][nt][2] + bb.x; o1.y = c[mt][nt][3] + bb.y;
            *(float2*)(C + (size_t)r0 * D_MODEL + col)       = o0;
            *(float2*)(C + (size_t)(r0 + 8) * D_MODEL + col) = o1;
        }
    }
#undef LDG_A
#undef LDG_B
#undef STS_A
#undef STS_B
}

// ===========================================================================
// tf32 mma.sync flash attention (non-causal, online softmax).
// CTA = 128 q-rows of one (b,h); 8 warps x 16 q-rows each; KV chunk 64.
// Each warp owns full KV width -> softmax + P handoff are intra-warp.
// Qs[m][e] stride 68 (scaled by 1/8, tf32), Ks[s][e] stride 68,
// Vs[s][e] stride 72 (all conflict-free for their fragment access patterns).
// P c-frag -> a-frag rearrangement via 8 shfl per 16x8 tile.
// ===========================================================================
#define AQ_STR 68
#define AK_STR 68
#define AV_STR 72
#define ATT_SMEM ((128 * AQ_STR + 64 * AK_STR + 64 * AV_STR) * 4)  // 70656 B

__global__ __launch_bounds__(256) void attention_mma_kernel(
    const float* __restrict__ Q, const float* __restrict__ K,
    const float* __restrict__ V, float* __restrict__ O)
{
    extern __shared__ float sm[];
    float* Qs = sm;                      // [128][68]
    float* Ks = sm + 128 * AQ_STR;       // [64][68]
    float* Vs = Ks + 64 * AK_STR;        // [64][72]

    const int tid = threadIdx.x;
    const int w = tid >> 5, l = tid & 31;
    const int g = l >> 2,  d = l & 3;
    const int b = blockIdx.z, h = blockIdx.y;
    const int q0 = blockIdx.x * 128;
    const int wrow = w * 16;

    // Stage Q tile (128x64), scale 1/8 folded into tf32 conversion.
    const float* Qg = Q + ((size_t)b * SEQLEN + q0) * D_MODEL + h * HDIM;
#pragma unroll
    for (int i = 0; i < 8; i++) {
        int v = i * 256 + tid;
        int r = v >> 4, e4 = (v & 15) << 2;
        float4 q4 = *(const float4*)(Qg + (size_t)r * D_MODEL + e4);
        *(uint4*)(Qs + r * AQ_STR + e4) =
            make_uint4(cvt_tf32(0.125f * q4.x), cvt_tf32(0.125f * q4.y),
                       cvt_tf32(0.125f * q4.z), cvt_tf32(0.125f * q4.w));
    }

    float m0 = -1e30f, m1 = -1e30f, ls0 = 0.f, ls1 = 0.f;
    float po[8][4];
#pragma unroll
    for (int nt = 0; nt < 8; nt++)
#pragma unroll
        for (int r = 0; r < 4; r++) po[nt][r] = 0.f;

    const int srcA = (l & 28) | (d >> 1);
    const int srcB = srcA + 2;

#pragma unroll 1
    for (int s0 = 0; s0 < SEQLEN; s0 += 64) {
        const float* Kg = K + ((size_t)b * SEQLEN + s0) * D_MODEL + h * HDIM;
        const float* Vg = V + ((size_t)b * SEQLEN + s0) * D_MODEL + h * HDIM;

        __syncthreads();   // protect Ks/Vs from previous chunk's readers
#pragma unroll
        for (int i = 0; i < 4; i++) {
            int v = i * 256 + tid;
            int r = v >> 4, e4 = (v & 15) << 2;
            float4 k4 = *(const float4*)(Kg + (size_t)r * D_MODEL + e4);
            *(uint4*)(Ks + r * AK_STR + e4) =
                make_uint4(cvt_tf32(k4.x), cvt_tf32(k4.y),
                           cvt_tf32(k4.z), cvt_tf32(k4.w));
            float4 v4 = *(const float4*)(Vg + (size_t)r * D_MODEL + e4);
            *(uint4*)(Vs + r * AV_STR + e4) =
                make_uint4(cvt_tf32(v4.x), cvt_tf32(v4.y),
                           cvt_tf32(v4.z), cvt_tf32(v4.w));
        }
        __syncthreads();

        // ---- S = (Q/8) K^T : warp rows [wrow, wrow+16), cols [0,64) ----
        float sc[8][4];
#pragma unroll
        for (int nt = 0; nt < 8; nt++)
#pragma unroll
            for (int r = 0; r < 4; r++) sc[nt][r] = 0.f;

#pragma unroll
        for (int kk = 0; kk < 8; kk++) {
            const int ko = kk * 8;
            const float* qp = Qs + (wrow + g) * AQ_STR + ko + d;
            uint32_t a0 = __float_as_uint(qp[0]);
            uint32_t a1 = __float_as_uint(qp[8 * AQ_STR]);
            uint32_t a2 = __float_as_uint(qp[4]);
            uint32_t a3 = __float_as_uint(qp[8 * AQ_STR + 4]);
#pragma unroll
            for (int nt = 0; nt < 8; nt++) {
                const float* kp = Ks + (nt * 8 + g) * AK_STR + ko + d;
                uint32_t b0 = __float_as_uint(kp[0]);
                uint32_t b1 = __float_as_uint(kp[4]);
                MMA_TF32(sc[nt], a0, a1, a2, a3, b0, b1);
            }
        }

        // ---- online softmax (rows g and g+8; quad lanes share a row) ----
        float rx0 = -1e30f, rx1 = -1e30f;
#pragma unroll
        for (int nt = 0; nt < 8; nt++) {
            rx0 = fmaxf(rx0, fmaxf(sc[nt][0], sc[nt][1]));
            rx1 = fmaxf(rx1, fmaxf(sc[nt][2], sc[nt][3]));
        }
        rx0 = fmaxf(rx0, __shfl_xor_sync(0xffffffffu, rx0, 1));
        rx0 = fmaxf(rx0, __shfl_xor_sync(0xffffffffu, rx0, 2));
        rx1 = fmaxf(rx1, __shfl_xor_sync(0xffffffffu, rx1, 1));
        rx1 = fmaxf(rx1, __shfl_xor_sync(0xffffffffu, rx1, 2));

        float nm0 = fmaxf(m0, rx0), nm1 = fmaxf(m1, rx1);
        float c0 = __expf(m0 - nm0), c1 = __expf(m1 - nm1);
        m0 = nm0; m1 = nm1;

        float sum0 = 0.f, sum1 = 0.f;
#pragma unroll
        for (int nt = 0; nt < 8; nt++) {
            sc[nt][0] = __expf(sc[nt][0] - m0);
            sc[nt][1] = __expf(sc[nt][1] - m0);
            sc[nt][2] = __expf(sc[nt][2] - m1);
            sc[nt][3] = __expf(sc[nt][3] - m1);
            sum0 += sc[nt][0] + sc[nt][1];
            sum1 += sc[nt][2] + sc[nt][3];
        }
        sum0 += __shfl_xor_sync(0xffffffffu, sum0, 1);
        sum0 += __shfl_xor_sync(0xffffffffu, sum0, 2);
        sum1 += __shfl_xor_sync(0xffffffffu, sum1, 1);
        sum1 += __shfl_xor_sync(0xffffffffu, sum1, 2);
        ls0 = ls0 * c0 + sum0;
        ls1 = ls1 * c1 + sum1;
#pragma unroll
        for (int nt = 0; nt < 8; nt++) {
            po[nt][0] *= c0; po[nt][1] *= c0;
            po[nt][2] *= c1; po[nt][3] *= c1;
        }

        // ---- O += P V : c-frag -> a-frag via shfl, B direct from Vs ----
#pragma unroll
        for (int kk = 0; kk < 8; kk++) {
            float v00 = __shfl_sync(0xffffffffu, sc[kk][0], srcA);
            float v01 = __shfl_sync(0xffffffffu, sc[kk][1], srcA);
            float v02 = __shfl_sync(0xffffffffu, sc[kk][0], srcB);
            float v03 = __shfl_sync(0xffffffffu, sc[kk][1], srcB);
            float v10 = __shfl_sync(0xffffffffu, sc[kk][2], srcA);
            float v11 = __shfl_sync(0xffffffffu, sc[kk][3], srcA);
            float v12 = __shfl_sync(0xffffffffu, sc[kk][2], srcB);
            float v13 = __shfl_sync(0xffffffffu, sc[kk][3], srcB);
            uint32_t a0 = cvt_tf32((d & 1) ? v01 : v00);
            uint32_t a2 = cvt_tf32((d & 1) ? v03 : v02);
            uint32_t a1 = cvt_tf32((d & 1) ? v11 : v10);
            uint32_t a3 = cvt_tf32((d & 1) ? v13 : v12);
#pragma unroll
            for (int nt = 0; nt < 8; nt++) {
                const float* vp = Vs + (kk * 8 + d) * AV_STR + nt * 8 + g;
                uint32_t b0 = __float_as_uint(vp[0]);
                uint32_t b1 = __float_as_uint(vp[4 * AV_STR]);
                MMA_TF32(po[nt], a0, a1, a2, a3, b0, b1);
            }
        }
    }

    // ---- epilogue: normalize and store ----
    const float i0 = 1.f / ls0, i1 = 1.f / ls1;
    float* Orow0 = O + ((size_t)b * SEQLEN + q0 + wrow + g) * D_MODEL + h * HDIM;
    float* Orow1 = Orow0 + 8 * D_MODEL;
#pragma unroll
    for (int nt = 0; nt < 8; nt++) {
        *(float2*)(Orow0 + nt * 8 + 2 * d) =
            make_float2(po[nt][0] * i0, po[nt][1] * i0);
        *(float2*)(Orow1 + nt * 8 + 2 * d) =
            make_float2(po[nt][2] * i1, po[nt][3] * i1);
    }
}

// ---------------------------------------------------------------------------
// Launch: tf32 mma projections -> tf32 mma flash attention -> out proj.
// ---------------------------------------------------------------------------
extern "C" void kernel_launch(void* const* d_in, const int* in_sizes, int n_in,
                              void* d_out, int out_size)
{
    (void)in_sizes; (void)n_in; (void)out_size;
    const float* queries = (const float*)d_in[0];
    const float* keys    = (const float*)d_in[1];
    const float* values  = (const float*)d_in[2];
    const float* Wq = (const float*)d_in[3];
    const float* bq = (const float*)d_in[4];
    const float* Wk = (const float*)d_in[5];
    const float* bk = (const float*)d_in[6];
    const float* Wv = (const float*)d_in[7];
    const float* bv = (const float*)d_in[8];
    const float* Wo = (const float*)d_in[9];
    const float* bo = (const float*)d_in[10];
    float* out = (float*)d_out;

    float *Qp, *Kp, *Vp, *AOp;
    cudaGetSymbolAddress((void**)&Qp,  g_Q);
    cudaGetSymbolAddress((void**)&Kp,  g_K);
    cudaGetSymbolAddress((void**)&Vp,  g_V);
    cudaGetSymbolAddress((void**)&AOp, g_AO);

    cudaFuncSetAttribute(gemm_tf32_kernel,
                         cudaFuncAttributeMaxDynamicSharedMemorySize, GEMM_SMEM);
    cudaFuncSetAttribute(attention_mma_kernel,
                         cudaFuncAttributeMaxDynamicSharedMemorySize, ATT_SMEM);

    dim3 gg(D_MODEL / 128, MROWS / 128);   // (8, 64)
    gemm_tf32_kernel<<<gg, 256, GEMM_SMEM>>>(queries, Wq, bq, Qp);
    gemm_tf32_kernel<<<gg, 256, GEMM_SMEM>>>(keys,    Wk, bk, Kp);
    gemm_tf32_kernel<<<gg, 256, GEMM_SMEM>>>(values,  Wv, bv, Vp);

    dim3 ga(SEQLEN / 128, NHEADS, BATCH);  // (16, 16, 4)
    attention_mma_kernel<<<ga, 256, ATT_SMEM>>>(Qp, Kp, Vp, AOp);

    gemm_tf32_kernel<<<gg, 256, GEMM_SMEM>>>(AOp, Wo, bo, out);
}